// round 17
// baseline (speedup 1.0000x reference)
#include <cuda_runtime.h>
#include <cuda_fp16.h>

#define TT   4096
#define NCH  32
#define NB   64
#define NP   511
#define PS   16
#define NTHREADS 512

// All-fp16 SMEM cascade, 4 buffers of 4112 halves.
// Base banks (byte/4 mod 32): B0h:0, B1h:8, B2h:16, B3h:24.
#define OFF_B0H   0        // x   -> a2
#define OFF_B1H   4112     // a1  -> cA3
#define OFF_B2H   8224     // cD1 -> cD3
#define OFF_B3H   12336    // cD2
#define SMEM_HALVES 16448
#define SMEM_BYTES  (SMEM_HALVES * 2)   // 32896 B -> 4 blocks/SM (threads bind)

// Transposed input scratch (fp16): xTh[b][n][t], contiguous in t.
__device__ __half g_xTh[(size_t)NB * NCH * TT];

// db4 decomposition filters (ptwt convention)
__device__ __constant__ float c_lo[8] = {
    -0.010597401784997278f,  0.032883011666982945f,  0.030841381835986965f,
    -0.18703481171888114f,  -0.02798376941698385f,   0.6308807679295904f,
     0.7148465705525415f,    0.23037781330885523f
};
__device__ __constant__ float c_hi[8] = {
    -0.23037781330885523f,   0.7148465705525415f,   -0.6308807679295904f,
    -0.02798376941698385f,   0.18703481171888114f,   0.030841381835986965f,
    -0.032883011666982945f, -0.010597401784997278f
};

// ---------------------------------------------------------------------------
// Pack 4 floats -> 4 halves (uint2, 8B store).
// ---------------------------------------------------------------------------
__device__ __forceinline__ void store_half4(__half* dst, int idx,
                                            float a, float b, float c, float d)
{
    __half2 h01 = __floats2half2_rn(a, b);
    __half2 h23 = __floats2half2_rn(c, d);
    uint2 u;
    u.x = *(const unsigned int*)&h01;
    u.y = *(const unsigned int*)&h23;
    *(uint2*)&dst[idx] = u;
}

// ---------------------------------------------------------------------------
// Kernel A: transpose (B, T, N) fp32 -> (B, N, T) fp16.
// Each 256-thread block handles a 128t x 32n tile (4 sub-tiles, 1 barrier).
// ---------------------------------------------------------------------------
__global__ __launch_bounds__(256)
void transpose_kernel(const float* __restrict__ x)
{
    __shared__ float tile[4][32][33];
    const int b   = blockIdx.y;
    const int t0  = blockIdx.x << 7;
    const int lin = threadIdx.x;

    {
        const int t  = lin >> 3;
        const int n4 = (lin & 7) << 2;
        #pragma unroll
        for (int s = 0; s < 4; s++) {
            const float4 v = *(const float4*)
                &x[((size_t)b * TT + t0 + (s << 5) + t) * NCH + n4];
            tile[s][t][n4 + 0] = v.x;
            tile[s][t][n4 + 1] = v.y;
            tile[s][t][n4 + 2] = v.z;
            tile[s][t][n4 + 3] = v.w;
        }
    }
    __syncthreads();
    {
        const int n  = lin >> 3;
        const int t4 = (lin & 7) << 2;
        __half* dstRow = &g_xTh[((size_t)b * NCH + n) * TT + t0];
        #pragma unroll
        for (int s = 0; s < 4; s++) {
            store_half4(dstRow, (s << 5) + t4,
                        tile[s][t4 + 0][n], tile[s][t4 + 1][n],
                        tile[s][t4 + 2][n], tile[s][t4 + 3][n]);
        }
    }
}

// ---------------------------------------------------------------------------
// One SWT stage, 4 outputs/thread, streaming-accumulate; fp16 in / fp32
// accumulate / fp16 out.  coef[e] = sum_j f[j]*in[t0 + e + D*(4-j)].
// ---------------------------------------------------------------------------
template<int D, int S, int W>
__device__ __forceinline__ void swt_stage_h(const __half* __restrict__ in,
                                            __half* __restrict__ loH,
                                            __half* __restrict__ hiH,
                                            int tid)
{
    #pragma unroll 1
    for (int k = 0; k < TT / 4 / NTHREADS; k++) {
        const int t0 = ((tid + k * NTHREADS) << 2);
        float lo[4] = {0.f, 0.f, 0.f, 0.f};
        float hi[4] = {0.f, 0.f, 0.f, 0.f};
        #pragma unroll
        for (int q = 0; q < W / 4; q++) {
            const int off = (t0 + S + 4 * q + TT) & (TT - 1);
            const uint2 u = *(const uint2*)&in[off];
            const float2 f01 = __half22float2(*(const __half2*)&u.x);
            const float2 f23 = __half22float2(*(const __half2*)&u.y);
            const float elem[4] = {f01.x, f01.y, f23.x, f23.y};
            #pragma unroll
            for (int idx = 0; idx < 4; idx++) {
                const int a = S + 4 * q + idx;
                #pragma unroll
                for (int e = 0; e < 4; e++) {
                    const int diff = a - e;
                    if (diff % D == 0) {
                        const int j = 4 - diff / D;
                        if (j >= 0 && j < 8) {
                            lo[e] = fmaf(c_lo[j], elem[idx], lo[e]);
                            hi[e] = fmaf(c_hi[j], elem[idx], hi[e]);
                        }
                    }
                }
            }
        }
        store_half4(loH, t0, lo[0], lo[1], lo[2], lo[3]);
        store_half4(hiH, t0, hi[0], hi[1], hi[2], hi[3]);
    }
}

// ---------------------------------------------------------------------------
// Flush one channel's 64B half-line for all patches.
// out float offset = p*2048 + chOff + 4j, j in [0,4); src = band[8p + s],
// s = 4j (patch covers band values 8p .. 8p+15).
// 4 consecutive lanes emit one contiguous 64B chunk — sector-coalesced.
// ---------------------------------------------------------------------------
__device__ __forceinline__ void flush_channel(const __half* __restrict__ band,
                                              float* __restrict__ dstBase,
                                              int chOff, int tid)
{
    for (int g = tid; g < NP * 4; g += NTHREADS) {
        const int p = g >> 2;
        const int j = g & 3;
        const uint2 u = *(const uint2*)&band[(p << 3) + (j << 2)];
        const float2 f01 = __half22float2(*(const __half2*)&u.x);
        const float2 f23 = __half22float2(*(const __half2*)&u.y);
        __stcs((float4*)&dstBase[(size_t)p * 2048 + chOff + (j << 2)],
               make_float4(f01.x, f01.y, f23.x, f23.y));
    }
}

// ---------------------------------------------------------------------------
// Kernel B: per-(b,n) row — 3-level SWT, all-fp16 SMEM staging.
// Output writes spread across phases: cD1 flushed during stage 2,
// cD2 during stage 3, [cA3|cD3] at the end. Flush-first within each phase
// so STGs drain under the FMA work.
// ---------------------------------------------------------------------------
__global__ __launch_bounds__(NTHREADS, 4)
void swt_patch_kernel(float* __restrict__ out)
{
    extern __shared__ __align__(16) __half smh[];

    const int b   = blockIdx.x >> 5;
    const int n   = blockIdx.x & 31;
    const int tid = threadIdx.x;

    __half* B0h = smh + OFF_B0H;   // x   -> a2
    __half* B1h = smh + OFF_B1H;   // a1  -> cA3
    __half* B2h = smh + OFF_B2H;   // cD1 -> cD3
    __half* B3h = smh + OFF_B3H;   // cD2

    float* dstBase = out + (size_t)b * NP * 2048 + (size_t)n * 64;

    // Phase L: copy fp16 row into SMEM (one 16B load+store per thread).
    const __half* xin = &g_xTh[((size_t)b * NCH + n) * TT];
    {
        const int i = tid << 3;    // 8 halves per thread, 512*8 = 4096
        *(uint4*)&B0h[i] = *(const uint4*)&xin[i];
    }
    __syncthreads();

    // Phase 1: stage1 (d=1): a1 -> B1h, cD1 -> B2h
    swt_stage_h<1, -4, 12>(B0h, B1h, B2h, tid);
    __syncthreads();

    // Phase 2: flush cD1 (ch3, reads B2h) + stage2 (d=2, reads B1h,
    // writes B0h/B3h) — disjoint buffers, no intra-phase barrier.
    flush_channel(B2h, dstBase, 48, tid);
    swt_stage_h<2, -8, 20>(B1h, B0h, B3h, tid);
    __syncthreads();

    // Phase 3: flush cD2 (ch2, reads B3h) + stage3 (d=4, reads B0h,
    // writes B1h (cA3, a1 dead) / B2h (cD3, cD1 flushed)).
    flush_channel(B3h, dstBase, 32, tid);
    swt_stage_h<4, -12, 32>(B0h, B1h, B2h, tid);
    __syncthreads();

    // Phase 4: flush [cA3|cD3] full lines (channels 0,1).
    // 8 consecutive lanes emit one 128B line.
    for (int g = tid; g < NP * 8; g += NTHREADS) {
        const int p  = g >> 3;
        const int w8 = g & 7;
        const int s4 = (w8 & 3) << 2;
        const __half* src = (w8 < 4) ? B1h : B2h;   // ch0 = cA3, ch1 = cD3
        const uint2 u = *(const uint2*)&src[(p << 3) + s4];
        const float2 f01 = __half22float2(*(const __half2*)&u.x);
        const float2 f23 = __half22float2(*(const __half2*)&u.y);
        __stcs((float4*)&dstBase[(size_t)p * 2048 + (w8 << 2)],
               make_float4(f01.x, f01.y, f23.x, f23.y));
    }
}

extern "C" void kernel_launch(void* const* d_in, const int* in_sizes, int n_in,
                              void* d_out, int out_size)
{
    const float* x = (const float*)d_in[0];
    float* out = (float*)d_out;
    (void)in_sizes; (void)n_in; (void)out_size;

    cudaFuncSetAttribute(swt_patch_kernel,
                         cudaFuncAttributeMaxDynamicSharedMemorySize,
                         SMEM_BYTES);

    dim3 tgrid(TT / 128, NB);
    transpose_kernel<<<tgrid, 256>>>(x);
    swt_patch_kernel<<<NB * NCH, NTHREADS, SMEM_BYTES>>>(out);
}